// round 7
// baseline (speedup 1.0000x reference)
#include <cuda_runtime.h>
#include <cuda_fp16.h>
#include <cstdint>
#include <cstddef>

typedef unsigned long long u64;
typedef unsigned int u32;

#define B_  8
#define N_  1024
#define C_  768
#define H_  12
#define D_  64
#define C3  2304
#define M_  8192   // B_*N_

// ---------------- scratch (device globals; no runtime allocation) ----------
__device__ float g_qkv [(size_t)M_ * C3];   // [8192, 2304] fp32
__device__ u64   g_sbits[3 * B_ * H_ * N_]; // [which][b][h][n] packed spikes
__device__ float g_psum[64 * C3];           // per row-block column sums
__device__ float g_psq [64 * C3];
__device__ float g_scale[C3];
__device__ float g_shift[C3];
// fp16 split operands
__device__ __half g_xhi [(size_t)M_ * C_];
__device__ __half g_xlo [(size_t)M_ * C_];
__device__ __half g_w1hi[(size_t)C3 * C_];
__device__ __half g_w1lo[(size_t)C3 * C_];
__device__ __half g_ahi [(size_t)M_ * C_];   // attention out split
__device__ __half g_alo [(size_t)M_ * C_];
__device__ __half g_w2hi[(size_t)C_ * C_];
__device__ __half g_w2lo[(size_t)C_ * C_];

// ======================= baseline-PTX helpers ===============================
__device__ __forceinline__ u32 smem_to_u32(const void* p) {
    u32 a;
    asm("{ .reg .u64 t; cvta.to.shared.u64 t, %1; cvt.u32.u64 %0, t; }"
        : "=r"(a) : "l"(p));
    return a;
}
__device__ __forceinline__ void cp16(u32 dst, const void* src) {
    asm volatile("cp.async.cg.shared.global [%0], [%1], 16;"
                 :: "r"(dst), "l"(src));
}
#define CP_COMMIT() asm volatile("cp.async.commit_group;" ::: "memory")
template <int NN> __device__ __forceinline__ void cp_wait() {
    asm volatile("cp.async.wait_group %0;" :: "n"(NN) : "memory");
}
__device__ __forceinline__ void ldsm4(u32* r, u32 addr) {
    asm volatile("ldmatrix.sync.aligned.m8n8.x4.shared.b16 {%0,%1,%2,%3}, [%4];"
                 : "=r"(r[0]), "=r"(r[1]), "=r"(r[2]), "=r"(r[3]) : "r"(addr));
}
__device__ __forceinline__ void mma_f16(float* c, const u32* a, const u32* b) {
    asm volatile(
        "mma.sync.aligned.m16n8k16.row.col.f32.f16.f16.f32 "
        "{%0,%1,%2,%3}, {%4,%5,%6,%7}, {%8,%9}, {%0,%1,%2,%3};"
        : "+f"(c[0]), "+f"(c[1]), "+f"(c[2]), "+f"(c[3])
        : "r"(a[0]), "r"(a[1]), "r"(a[2]), "r"(a[3]), "r"(b[0]), "r"(b[1]));
}

// ======================= fp16 split (x = hi + lo) ===========================
__global__ __launch_bounds__(256)
void split_f16(const float* __restrict__ in, __half* __restrict__ hi,
               __half* __restrict__ lo, int n4)
{
    int i = blockIdx.x * 256 + threadIdx.x;
    if (i >= n4) return;
    float4 v = ((const float4*)in)[i];
    __half h0 = __float2half_rn(v.x), h1 = __float2half_rn(v.y);
    __half h2 = __float2half_rn(v.z), h3 = __float2half_rn(v.w);
    __half l0 = __float2half_rn(v.x - __half2float(h0));
    __half l1 = __float2half_rn(v.y - __half2float(h1));
    __half l2 = __float2half_rn(v.z - __half2float(h2));
    __half l3 = __float2half_rn(v.w - __half2float(h3));
    __half2 p;
    p.x = h0; p.y = h1; ((__half2*)hi)[i * 2]     = p;
    p.x = h2; p.y = h3; ((__half2*)hi)[i * 2 + 1] = p;
    p.x = l0; p.y = l1; ((__half2*)lo)[i * 2]     = p;
    p.x = l2; p.y = l3; ((__half2*)lo)[i * 2 + 1] = p;
}

// ======================= split-fp16 mma.sync GEMM ===========================
// C[M,N](fp32) = Ahi*Bhi^T + Ahi*Blo^T + Alo*Bhi^T (+bias), K=768.
// 128x128 CTA tile, BK=32, 8 warps (2x4), warp tile 64x32.
// 2-stage cp.async pipeline, ONE __syncthreads per K-iteration.
// STATS: emit per-CTA column sum/sumsq partials for BN (deterministic order).
#define TILE_PB  10240                  // 128*40*2 bytes
#define STAGE_B  (4 * TILE_PB)          // Ahi,Alo,Bhi,Blo
#define GEMM_SMEM (2 * STAGE_B)         // 81920

template <bool BIAS, bool STATS>
__global__ __launch_bounds__(256)
void gemm_mma(const __half* __restrict__ Ahi, const __half* __restrict__ Alo,
              const __half* __restrict__ Bhi, const __half* __restrict__ Blo,
              const float* __restrict__ bias, float* __restrict__ C, int ldC)
{
    extern __shared__ char smem[];
    const u32 base = smem_to_u32(smem);
    __shared__ float scs[8][32];
    __shared__ float scq[8][32];

    const int tid  = threadIdx.x;
    const int wid  = tid >> 5, lane = tid & 31;
    const int wm   = wid >> 2, wn = wid & 3;
    const int n0   = blockIdx.x * 128, m0 = blockIdx.y * 128;

    const int jA = lane >> 3, iA = lane & 7;
    const int mA = iA + (jA & 1) * 8;
    const int kA = (jA >> 1) * 8;
    const int nB = iA + (lane >> 4) * 8;
    const int kB = (jA & 1) * 8;

    const __half* s0 = Ahi + (size_t)m0 * 768;
    const __half* s1 = Alo + (size_t)m0 * 768;
    const __half* s2 = Bhi + (size_t)n0 * 768;
    const __half* s3 = Blo + (size_t)n0 * 768;

    float acc[4][4][4];
#pragma unroll
    for (int mi = 0; mi < 4; ++mi)
#pragma unroll
        for (int ni = 0; ni < 4; ++ni)
#pragma unroll
            for (int k = 0; k < 4; ++k) acc[mi][ni][k] = 0.f;

#define LOAD_STAGE(stg, k0) do {                                              \
        u32 sb_ = base + (stg) * STAGE_B;                                     \
        _Pragma("unroll")                                                     \
        for (int it = 0; it < 8; ++it) {                                      \
            const __half* src =                                               \
                (it >> 1) == 0 ? s0 : (it >> 1) == 1 ? s1                     \
              : (it >> 1) == 2 ? s2 : s3;                                     \
            int idx = tid + (it & 1) * 256;                                   \
            int r = idx >> 2, q = idx & 3;                                    \
            cp16(sb_ + (it >> 1) * TILE_PB + r * 80 + q * 16,                 \
                 src + (size_t)r * 768 + (k0) + q * 8);                       \
        }                                                                     \
    } while (0)

    LOAD_STAGE(0, 0);
    CP_COMMIT();

    for (int itk = 0; itk < 24; ++itk) {
        cp_wait<0>();
        __syncthreads();   // loads for slot itk visible; all reads of the other slot done
        if (itk + 1 < 24) { LOAD_STAGE((itk + 1) & 1, (itk + 1) * 32); CP_COMMIT(); }

        const u32 sb  = base + (itk & 1) * STAGE_B;
        const u32 aHi = sb, aLo = sb + TILE_PB;
        const u32 bHi = sb + 2 * TILE_PB, bLo = sb + 3 * TILE_PB;

#pragma unroll
        for (int ks = 0; ks < 2; ++ks) {
            u32 ah[4][4], al[4][4], bh[2][4], bl[2][4];
#pragma unroll
            for (int p = 0; p < 2; ++p) {
                u32 ro = (u32)((wn * 32 + p * 16 + nB) * 80 + (ks * 16 + kB) * 2);
                ldsm4(bh[p], bHi + ro);
                ldsm4(bl[p], bLo + ro);
            }
#pragma unroll
            for (int mi = 0; mi < 4; ++mi) {
                u32 ro = (u32)((wm * 64 + mi * 16 + mA) * 80 + (ks * 16 + kA) * 2);
                ldsm4(ah[mi], aHi + ro);
                ldsm4(al[mi], aLo + ro);
            }
#pragma unroll
            for (int mi = 0; mi < 4; ++mi)
#pragma unroll
                for (int ni = 0; ni < 4; ++ni) {
                    const u32* BH = &bh[ni >> 1][(ni & 1) * 2];
                    const u32* BL = &bl[ni >> 1][(ni & 1) * 2];
                    mma_f16(acc[mi][ni], ah[mi], BH);
                    mma_f16(acc[mi][ni], ah[mi], BL);
                    mma_f16(acc[mi][ni], al[mi], BH);
                }
        }
    }

    // ---- BN stage-1 partials (deterministic), qkv GEMM only ----
    if (STATS) {
        float cs[8], cq[8];
#pragma unroll
        for (int ni = 0; ni < 4; ++ni)
#pragma unroll
            for (int p = 0; p < 2; ++p) {
                float s = 0.f, q = 0.f;
#pragma unroll
                for (int mi = 0; mi < 4; ++mi) {
                    float a0 = acc[mi][ni][p], a1 = acc[mi][ni][p + 2];
                    s += a0 + a1;
                    q += a0 * a0 + a1 * a1;
                }
                cs[ni * 2 + p] = s; cq[ni * 2 + p] = q;
            }
#pragma unroll
        for (int off = 4; off < 32; off <<= 1)
#pragma unroll
            for (int j = 0; j < 8; ++j) {
                cs[j] += __shfl_xor_sync(0xFFFFFFFFu, cs[j], off);
                cq[j] += __shfl_xor_sync(0xFFFFFFFFu, cq[j], off);
            }
        if (lane < 4) {
#pragma unroll
            for (int j = 0; j < 8; ++j) {
                int cl = (j >> 1) * 8 + lane * 2 + (j & 1);
                scs[wid][cl] = cs[j];
                scq[wid][cl] = cq[j];
            }
        }
        __syncthreads();
        if (tid < 128) {
            int cl = tid & 31, w = tid >> 5;
            float s = scs[w][cl] + scs[w + 4][cl];
            float q = scq[w][cl] + scq[w + 4][cl];
            g_psum[(size_t)blockIdx.y * C3 + n0 + tid] = s;
            g_psq [(size_t)blockIdx.y * C3 + n0 + tid] = q;
        }
    }

    // ---- write C ----
    const int mrow = wm * 64 + (lane >> 2);
    const int ncol = wn * 32 + (lane & 3) * 2;
#pragma unroll
    for (int mi = 0; mi < 4; ++mi) {
#pragma unroll
        for (int ni = 0; ni < 4; ++ni) {
            int col = n0 + ncol + ni * 8;
            size_t r0 = (size_t)(m0 + mrow + mi * 16) * ldC + col;
            size_t r1 = r0 + 8 * (size_t)ldC;
            float2 v0, v1;
            v0.x = acc[mi][ni][0]; v0.y = acc[mi][ni][1];
            v1.x = acc[mi][ni][2]; v1.y = acc[mi][ni][3];
            if (BIAS) {
                float b0 = bias[col], b1 = bias[col + 1];
                v0.x += b0; v0.y += b1; v1.x += b0; v1.y += b1;
            }
            *(float2*)(C + r0) = v0;
            *(float2*)(C + r1) = v1;
        }
    }
#undef LOAD_STAGE
}

// ---------------- BN finalize: reduce 64 row-block partials ----------------
__global__ __launch_bounds__(256)
void bn_finalize(const float* __restrict__ gamma, const float* __restrict__ beta)
{
    int c = blockIdx.x * 256 + threadIdx.x;
    float s = 0.f, q = 0.f;
    for (int i = 0; i < 64; ++i) { s += g_psum[(size_t)i * C3 + c]; q += g_psq[(size_t)i * C3 + c]; }
    float mean = s * (1.f / M_);
    float var  = q * (1.f / M_) - mean * mean;
    float rs   = rsqrtf(var + 1e-5f);
    float sc   = gamma[c] * rs;
    g_scale[c] = sc;
    g_shift[c] = beta[c] - mean * sc;
}

// ---------------- fused BN-apply + multistep LIF + bit-pack ----------------
__global__ __launch_bounds__(256)
void bnlif(const float* __restrict__ qkv)
{
    int gid   = blockIdx.x * 256 + threadIdx.x;
    int n     = gid & 1023;
    int t     = gid >> 10;
    int h     = t % H_;
    int which = t / H_;
    int c0    = which * C_ + h * D_;

    u64 bits[B_];
#pragma unroll
    for (int b = 0; b < B_; ++b) bits[b] = 0ull;

#pragma unroll
    for (int dq = 0; dq < 4; ++dq) {
        int cb = c0 + dq * 16;
        float sc[16], sh[16];
#pragma unroll
        for (int q4 = 0; q4 < 4; ++q4) {
            *(float4*)(sc + q4 * 4) = *(const float4*)(g_scale + cb + q4 * 4);
            *(float4*)(sh + q4 * 4) = *(const float4*)(g_shift + cb + q4 * 4);
        }
        float v[16];
#pragma unroll
        for (int d = 0; d < 16; ++d) v[d] = 0.f;

#pragma unroll
        for (int b = 0; b < B_; ++b) {
            const float* row = qkv + (size_t)(b * N_ + n) * C3 + cb;
            float xv[16];
#pragma unroll
            for (int q4 = 0; q4 < 4; ++q4)
                *(float4*)(xv + q4 * 4) = *(const float4*)(row + q4 * 4);
#pragma unroll
            for (int d = 0; d < 16; ++d) {
                float y = fmaf(xv[d], sc[d], sh[d]);
                v[d] = 0.5f * (v[d] + y);
                if (v[d] >= 1.0f) {
                    bits[b] |= 1ull << (dq * 16 + d);
                    v[d] = 0.f;
                }
            }
        }
    }
#pragma unroll
    for (int b = 0; b < B_; ++b)
        g_sbits[((size_t)(which * B_ + b) * H_ + h) * N_ + n] = bits[b];
}

// ============== attention v2: full tensor-core (QK mma, exp, PV mma) ========
#define A2_Q    0                       // 128 x 72 halves
#define A2_K    18432                   // 128 x 72 halves
#define A2_VT   36864                   // 96 x 136 halves
#define A2_EH   62976                   // 128 x 136 halves
#define A2_EL   97792                   // 128 x 136 halves
#define A2_DEN  132608                  // 128 floats
#define ATTN2_SMEM 133120

__global__ __launch_bounds__(256)
void attn2(__half* __restrict__ ohi, __half* __restrict__ olo)
{
    extern __shared__ char sm[];
    const u32 base = smem_to_u32(sm);
    const int tid = threadIdx.x, lane = tid & 31, wid = tid >> 5;
    const int bh = blockIdx.x, rt = blockIdx.y;
    const int b = bh / H_, h = bh % H_;

    const u64* qb = g_sbits + ((size_t)(0 * B_ + b) * H_ + h) * N_ + rt * 128;
    const u64* kb = g_sbits + ((size_t)(1 * B_ + b) * H_ + h) * N_;
    const u64* vb = g_sbits + ((size_t)(2 * B_ + b) * H_ + h) * N_;

    __half* sQ  = (__half*)(sm + A2_Q);
    __half* sK  = (__half*)(sm + A2_K);
    __half* sVt = (__half*)(sm + A2_VT);
    __half* sEh = (__half*)(sm + A2_EH);
    __half* sEl = (__half*)(sm + A2_EL);
    float*  den = (float*)(sm + A2_DEN);

    const int iA = lane & 7, jA = lane >> 3;
    const int mA = iA + (jA & 1) * 8;
    const int kA = (jA >> 1) * 8;
    const int nB = iA + (lane >> 4) * 8;
    const int kB = (jA & 1) * 8;

    const int wmQ = wid >> 2, wnQ = wid & 3;   // QK: 2x4
    const int wmP = wid >> 1, wnP = wid & 1;   // PV: 4x2

    {
        int j = tid >> 1, hs = tid & 1;
        u64 qr = qb[j] >> (hs * 32);
        __half* dst = sQ + j * 72 + hs * 32;
#pragma unroll
        for (int d = 0; d < 32; ++d)
            dst[d] = __float2half_rn((float)((qr >> d) & 1ull));
    }

    float oacc[2][5][4];
#pragma unroll
    for (int mi = 0; mi < 2; ++mi)
#pragma unroll
        for (int ni = 0; ni < 5; ++ni)
#pragma unroll
            for (int k = 0; k < 4; ++k) oacc[mi][ni][k] = 0.f;

    for (int jt = 0; jt < 8; ++jt) {
        {
            int j = tid >> 1, hs = tid & 1;
            u64 kr = kb[jt * 128 + j] >> (hs * 32);
            __half* dst = sK + j * 72 + hs * 32;
#pragma unroll
            for (int d = 0; d < 32; ++d)
                dst[d] = __float2half_rn((float)((kr >> d) & 1ull));
        }
#pragma unroll 4
        for (int it = 0; it < 48; ++it) {
            int idx = it * 256 + tid;
            int d = idx >> 7, j = idx & 127;
            float v = 0.f;
            if (d < 64) v = (float)((vb[jt * 128 + j] >> d) & 1ull);
            else if (d == 64) v = 1.f;
            sVt[d * 136 + j] = __float2half_rn(v);
        }
        __syncthreads();

#pragma unroll
        for (int nh = 0; nh < 2; ++nh) {
            float sacc[4][2][4];
#pragma unroll
            for (int mi = 0; mi < 4; ++mi)
#pragma unroll
                for (int nj = 0; nj < 2; ++nj)
#pragma unroll
                    for (int k = 0; k < 4; ++k) sacc[mi][nj][k] = 0.f;
#pragma unroll
            for (int ks = 0; ks < 4; ++ks) {
                u32 aq[4][4], bk[4];
#pragma unroll
                for (int mi = 0; mi < 4; ++mi)
                    ldsm4(aq[mi], base + A2_Q +
                          (u32)(((wmQ * 64 + mi * 16 + mA) * 72 + ks * 16 + kA) * 2));
                ldsm4(bk, base + A2_K +
                      (u32)(((wnQ * 32 + nh * 16 + nB) * 72 + ks * 16 + kB) * 2));
#pragma unroll
                for (int mi = 0; mi < 4; ++mi)
#pragma unroll
                    for (int nj = 0; nj < 2; ++nj)
                        mma_f16(sacc[mi][nj], aq[mi], &bk[nj * 2]);
            }
            const float CEXP = 0.18033688011f;   // log2(e)/8
#pragma unroll
            for (int mi = 0; mi < 4; ++mi)
#pragma unroll
                for (int nj = 0; nj < 2; ++nj) {
                    int r0 = wmQ * 64 + mi * 16 + (lane >> 2);
                    int c0 = wnQ * 32 + nh * 16 + nj * 8 + (lane & 3) * 2;
                    float e0 = exp2f(sacc[mi][nj][0] * CEXP);
                    float e1 = exp2f(sacc[mi][nj][1] * CEXP);
                    float e2 = exp2f(sacc[mi][nj][2] * CEXP);
                    float e3 = exp2f(sacc[mi][nj][3] * CEXP);
                    __half h0 = __float2half_rn(e0), h1 = __float2half_rn(e1);
                    __half h2 = __float2half_rn(e2), h3 = __float2half_rn(e3);
                    __half2 p;
                    p.x = h0; p.y = h1; *(__half2*)(sEh + r0 * 136 + c0) = p;
                    p.x = h2; p.y = h3; *(__half2*)(sEh + (r0 + 8) * 136 + c0) = p;
                    p.x = __float2half_rn(e0 - __half2float(h0));
                    p.y = __float2half_rn(e1 - __half2float(h1));
                    *(__half2*)(sEl + r0 * 136 + c0) = p;
                    p.x = __float2half_rn(e2 - __half2float(h2));
                    p.y = __float2half_rn(e3 - __half2float(h3));
                    *(__half2*)(sEl + (r0 + 8) * 136 + c0) = p;
                }
        }
        __syncthreads();

#pragma unroll
        for (int ks = 0; ks < 8; ++ks) {
            u32 aeh[2][4], ael[2][4], bv[3][4];
#pragma unroll
            for (int mi = 0; mi < 2; ++mi) {
                u32 ro = (u32)(((wmP * 32 + mi * 16 + mA) * 136 + ks * 16 + kA) * 2);
                ldsm4(aeh[mi], base + A2_EH + ro);
                ldsm4(ael[mi], base + A2_EL + ro);
            }
#pragma unroll
            for (int p = 0; p < 3; ++p)
                ldsm4(bv[p], base + A2_VT +
                      (u32)(((wnP * 40 + p * 16 + nB) * 136 + ks * 16 + kB) * 2));
#pragma unroll
            for (int mi = 0; mi < 2; ++mi)
#pragma unroll
                for (int ni = 0; ni < 5; ++ni) {
                    const u32* bb = (ni < 4) ? &bv[ni >> 1][(ni & 1) * 2] : &bv[2][0];
                    mma_f16(oacc[mi][ni], aeh[mi], bb);
                    mma_f16(oacc[mi][ni], ael[mi], bb);
                }
        }
        __syncthreads();
    }

    if (wnP == 1 && (lane & 3) == 0) {
#pragma unroll
        for (int mi = 0; mi < 2; ++mi) {
            int r0 = wmP * 32 + mi * 16 + (lane >> 2);
            den[r0]     = oacc[mi][3][0];
            den[r0 + 8] = oacc[mi][3][2];
        }
    }
    __syncthreads();

    const int nlim = (wnP == 0) ? 5 : 3;
#pragma unroll
    for (int mi = 0; mi < 2; ++mi) {
        int r0 = wmP * 32 + mi * 16 + (lane >> 2);
        float i0 = 1.f / den[r0], i1 = 1.f / den[r0 + 8];
        size_t gr0 = ((size_t)(b * N_ + rt * 128 + r0)) * C_ + h * 64;
        size_t gr1 = gr0 + 8 * (size_t)C_;
#pragma unroll
        for (int ni = 0; ni < 5; ++ni) {
            if (ni >= nlim) break;
            int c0 = wnP * 40 + ni * 8 + (lane & 3) * 2;
            float v0 = oacc[mi][ni][0] * i0, v1 = oacc[mi][ni][1] * i0;
            float v2 = oacc[mi][ni][2] * i1, v3 = oacc[mi][ni][3] * i1;
            __half h0 = __float2half_rn(v0), h1 = __float2half_rn(v1);
            __half h2 = __float2half_rn(v2), h3 = __float2half_rn(v3);
            __half2 p;
            p.x = h0; p.y = h1; *(__half2*)(ohi + gr0 + c0) = p;
            p.x = h2; p.y = h3; *(__half2*)(ohi + gr1 + c0) = p;
            p.x = __float2half_rn(v0 - __half2float(h0));
            p.y = __float2half_rn(v1 - __half2float(h1));
            *(__half2*)(olo + gr0 + c0) = p;
            p.x = __float2half_rn(v2 - __half2float(h2));
            p.y = __float2half_rn(v3 - __half2float(h3));
            *(__half2*)(olo + gr1 + c0) = p;
        }
    }
}

// ---------------- launch ----------------------------------------------------
extern "C" void kernel_launch(void* const* d_in, const int* in_sizes, int n_in,
                              void* d_out, int out_size)
{
    const float* x      = (const float*)d_in[0];
    const float* w_qkv  = (const float*)d_in[1];
    const float* gamma  = (const float*)d_in[2];
    const float* beta   = (const float*)d_in[3];
    const float* w_proj = (const float*)d_in[4];
    const float* b_proj = (const float*)d_in[5];
    float* out = (float*)d_out;

    float *qkv = nullptr;
    __half *xhi, *xlo, *w1hi, *w1lo, *ahi, *alo, *w2hi, *w2lo;
    cudaGetSymbolAddress((void**)&qkv,  g_qkv);
    cudaGetSymbolAddress((void**)&xhi,  g_xhi);
    cudaGetSymbolAddress((void**)&xlo,  g_xlo);
    cudaGetSymbolAddress((void**)&w1hi, g_w1hi);
    cudaGetSymbolAddress((void**)&w1lo, g_w1lo);
    cudaGetSymbolAddress((void**)&ahi,  g_ahi);
    cudaGetSymbolAddress((void**)&alo,  g_alo);
    cudaGetSymbolAddress((void**)&w2hi, g_w2hi);
    cudaGetSymbolAddress((void**)&w2lo, g_w2lo);

    cudaFuncSetAttribute(attn2,
                         cudaFuncAttributeMaxDynamicSharedMemorySize, ATTN2_SMEM);
    cudaFuncSetAttribute(gemm_mma<false, true>,
                         cudaFuncAttributeMaxDynamicSharedMemorySize, GEMM_SMEM);
    cudaFuncSetAttribute(gemm_mma<true, false>,
                         cudaFuncAttributeMaxDynamicSharedMemorySize, GEMM_SMEM);

    // 0) fp16 splits of x, w_qkv, w_proj
    split_f16<<<(M_ * C_ / 4 + 255) / 256, 256>>>(x, xhi, xlo, M_ * C_ / 4);
    split_f16<<<(C3 * C_ / 4 + 255) / 256, 256>>>(w_qkv, w1hi, w1lo, C3 * C_ / 4);
    split_f16<<<(C_ * C_ / 4 + 255) / 256, 256>>>(w_proj, w2hi, w2lo, C_ * C_ / 4);
    // 1) qkv = x @ w_qkv^T (mma.sync split-fp16) + fused BN stage-1 partials
    gemm_mma<false, true><<<dim3(C3 / 128, M_ / 128), 256, GEMM_SMEM>>>(
        xhi, xlo, w1hi, w1lo, nullptr, qkv, C3);
    // 2) BN finalize (reduce 64 row-block partials)
    bn_finalize<<<9, 256>>>(gamma, beta);
    // 3) BN apply + LIF + bit-pack
    bnlif<<<144, 256>>>(qkv);
    // 4) tensor-core spiking attention -> fp16 split output
    attn2<<<dim3(B_ * H_, 8), 256, ATTN2_SMEM>>>(ahi, alo);
    // 5) out = attn @ w_proj^T + b_proj (mma.sync split-fp16)
    gemm_mma<true, false><<<dim3(C_ / 128, M_ / 128), 256, GEMM_SMEM>>>(
        ahi, alo, w2hi, w2lo, b_proj, out, C_);
}

// round 8
// speedup vs baseline: 1.0001x; 1.0001x over previous
#include <cuda_runtime.h>
#include <cuda_fp16.h>
#include <cstdint>
#include <cstddef>

typedef unsigned long long u64;
typedef unsigned int u32;

#define B_  8
#define N_  1024
#define C_  768
#define H_  12
#define D_  64
#define C3  2304
#define M_  8192   // B_*N_

// ---------------- scratch (device globals; no runtime allocation) ----------
__device__ float g_qkv [(size_t)M_ * C3];   // [8192, 2304] fp32
__device__ u64   g_sbits[3 * B_ * H_ * N_]; // [which][b][h][n] packed spikes
__device__ float g_psum[64 * C3];           // per row-block column sums
__device__ float g_psq [64 * C3];
__device__ float g_scale[C3];
__device__ float g_shift[C3];
// fp16 split operands
__device__ __half g_xhi [(size_t)M_ * C_];
__device__ __half g_xlo [(size_t)M_ * C_];
__device__ __half g_w1hi[(size_t)C3 * C_];
__device__ __half g_w1lo[(size_t)C3 * C_];
__device__ __half g_ahi [(size_t)M_ * C_];   // attention out split
__device__ __half g_alo [(size_t)M_ * C_];
__device__ __half g_w2hi[(size_t)C_ * C_];
__device__ __half g_w2lo[(size_t)C_ * C_];

// ======================= baseline-PTX helpers ===============================
__device__ __forceinline__ u32 smem_to_u32(const void* p) {
    u32 a;
    asm("{ .reg .u64 t; cvta.to.shared.u64 t, %1; cvt.u32.u64 %0, t; }"
        : "=r"(a) : "l"(p));
    return a;
}
__device__ __forceinline__ void cp16(u32 dst, const void* src) {
    asm volatile("cp.async.cg.shared.global [%0], [%1], 16;"
                 :: "r"(dst), "l"(src));
}
#define CP_COMMIT() asm volatile("cp.async.commit_group;" ::: "memory")
template <int NN> __device__ __forceinline__ void cp_wait() {
    asm volatile("cp.async.wait_group %0;" :: "n"(NN) : "memory");
}
__device__ __forceinline__ void ldsm4(u32* r, u32 addr) {
    asm volatile("ldmatrix.sync.aligned.m8n8.x4.shared.b16 {%0,%1,%2,%3}, [%4];"
                 : "=r"(r[0]), "=r"(r[1]), "=r"(r[2]), "=r"(r[3]) : "r"(addr));
}
__device__ __forceinline__ void mma_f16(float* c, const u32* a, const u32* b) {
    asm volatile(
        "mma.sync.aligned.m16n8k16.row.col.f32.f16.f16.f32 "
        "{%0,%1,%2,%3}, {%4,%5,%6,%7}, {%8,%9}, {%0,%1,%2,%3};"
        : "+f"(c[0]), "+f"(c[1]), "+f"(c[2]), "+f"(c[3])
        : "r"(a[0]), "r"(a[1]), "r"(a[2]), "r"(a[3]), "r"(b[0]), "r"(b[1]));
}

// ======================= fp16 split (x = hi + lo) ===========================
__global__ __launch_bounds__(256)
void split_f16(const float* __restrict__ in, __half* __restrict__ hi,
               __half* __restrict__ lo, int n4)
{
    int i = blockIdx.x * 256 + threadIdx.x;
    if (i >= n4) return;
    float4 v = ((const float4*)in)[i];
    __half h0 = __float2half_rn(v.x), h1 = __float2half_rn(v.y);
    __half h2 = __float2half_rn(v.z), h3 = __float2half_rn(v.w);
    __half l0 = __float2half_rn(v.x - __half2float(h0));
    __half l1 = __float2half_rn(v.y - __half2float(h1));
    __half l2 = __float2half_rn(v.z - __half2float(h2));
    __half l3 = __float2half_rn(v.w - __half2float(h3));
    __half2 p;
    p.x = h0; p.y = h1; ((__half2*)hi)[i * 2]     = p;
    p.x = h2; p.y = h3; ((__half2*)hi)[i * 2 + 1] = p;
    p.x = l0; p.y = l1; ((__half2*)lo)[i * 2]     = p;
    p.x = l2; p.y = l3; ((__half2*)lo)[i * 2 + 1] = p;
}

// ======================= split-fp16 mma.sync GEMM ===========================
// C[M,N](fp32) = Ahi*Bhi^T + Ahi*Blo^T + Alo*Bhi^T (+bias), K=768.
// 128x128 CTA tile, BK=32, 8 warps (2x4), warp tile 64x32.
// 2-stage cp.async pipeline, ONE __syncthreads per K-iteration.
// STATS: emit per-CTA column sum/sumsq partials for BN (deterministic order).
#define TILE_PB  10240                  // 128*40*2 bytes
#define STAGE_B  (4 * TILE_PB)          // Ahi,Alo,Bhi,Blo
#define GEMM_SMEM (2 * STAGE_B)         // 81920

template <bool BIAS, bool STATS>
__global__ __launch_bounds__(256)
void gemm_mma(const __half* __restrict__ Ahi, const __half* __restrict__ Alo,
              const __half* __restrict__ Bhi, const __half* __restrict__ Blo,
              const float* __restrict__ bias, float* __restrict__ C, int ldC)
{
    extern __shared__ char smem[];
    const u32 base = smem_to_u32(smem);
    __shared__ float scs[8][32];
    __shared__ float scq[8][32];

    const int tid  = threadIdx.x;
    const int wid  = tid >> 5, lane = tid & 31;
    const int wm   = wid >> 2, wn = wid & 3;
    const int n0   = blockIdx.x * 128, m0 = blockIdx.y * 128;

    const int jA = lane >> 3, iA = lane & 7;
    const int mA = iA + (jA & 1) * 8;
    const int kA = (jA >> 1) * 8;
    const int nB = iA + (lane >> 4) * 8;
    const int kB = (jA & 1) * 8;

    const __half* s0 = Ahi + (size_t)m0 * 768;
    const __half* s1 = Alo + (size_t)m0 * 768;
    const __half* s2 = Bhi + (size_t)n0 * 768;
    const __half* s3 = Blo + (size_t)n0 * 768;

    float acc[4][4][4];
#pragma unroll
    for (int mi = 0; mi < 4; ++mi)
#pragma unroll
        for (int ni = 0; ni < 4; ++ni)
#pragma unroll
            for (int k = 0; k < 4; ++k) acc[mi][ni][k] = 0.f;

#define LOAD_STAGE(stg, k0) do {                                              \
        u32 sb_ = base + (stg) * STAGE_B;                                     \
        _Pragma("unroll")                                                     \
        for (int it = 0; it < 8; ++it) {                                      \
            const __half* src =                                               \
                (it >> 1) == 0 ? s0 : (it >> 1) == 1 ? s1                     \
              : (it >> 1) == 2 ? s2 : s3;                                     \
            int idx = tid + (it & 1) * 256;                                   \
            int r = idx >> 2, q = idx & 3;                                    \
            cp16(sb_ + (it >> 1) * TILE_PB + r * 80 + q * 16,                 \
                 src + (size_t)r * 768 + (k0) + q * 8);                       \
        }                                                                     \
    } while (0)

    LOAD_STAGE(0, 0);
    CP_COMMIT();

    for (int itk = 0; itk < 24; ++itk) {
        cp_wait<0>();
        __syncthreads();   // loads for slot itk visible; all reads of the other slot done
        if (itk + 1 < 24) { LOAD_STAGE((itk + 1) & 1, (itk + 1) * 32); CP_COMMIT(); }

        const u32 sb  = base + (itk & 1) * STAGE_B;
        const u32 aHi = sb, aLo = sb + TILE_PB;
        const u32 bHi = sb + 2 * TILE_PB, bLo = sb + 3 * TILE_PB;

#pragma unroll
        for (int ks = 0; ks < 2; ++ks) {
            u32 ah[4][4], al[4][4], bh[2][4], bl[2][4];
#pragma unroll
            for (int p = 0; p < 2; ++p) {
                u32 ro = (u32)((wn * 32 + p * 16 + nB) * 80 + (ks * 16 + kB) * 2);
                ldsm4(bh[p], bHi + ro);
                ldsm4(bl[p], bLo + ro);
            }
#pragma unroll
            for (int mi = 0; mi < 4; ++mi) {
                u32 ro = (u32)((wm * 64 + mi * 16 + mA) * 80 + (ks * 16 + kA) * 2);
                ldsm4(ah[mi], aHi + ro);
                ldsm4(al[mi], aLo + ro);
            }
#pragma unroll
            for (int mi = 0; mi < 4; ++mi)
#pragma unroll
                for (int ni = 0; ni < 4; ++ni) {
                    const u32* BH = &bh[ni >> 1][(ni & 1) * 2];
                    const u32* BL = &bl[ni >> 1][(ni & 1) * 2];
                    mma_f16(acc[mi][ni], ah[mi], BH);
                    mma_f16(acc[mi][ni], ah[mi], BL);
                    mma_f16(acc[mi][ni], al[mi], BH);
                }
        }
    }

    // ---- BN stage-1 partials (deterministic), qkv GEMM only ----
    if (STATS) {
        float cs[8], cq[8];
#pragma unroll
        for (int ni = 0; ni < 4; ++ni)
#pragma unroll
            for (int p = 0; p < 2; ++p) {
                float s = 0.f, q = 0.f;
#pragma unroll
                for (int mi = 0; mi < 4; ++mi) {
                    float a0 = acc[mi][ni][p], a1 = acc[mi][ni][p + 2];
                    s += a0 + a1;
                    q += a0 * a0 + a1 * a1;
                }
                cs[ni * 2 + p] = s; cq[ni * 2 + p] = q;
            }
#pragma unroll
        for (int off = 4; off < 32; off <<= 1)
#pragma unroll
            for (int j = 0; j < 8; ++j) {
                cs[j] += __shfl_xor_sync(0xFFFFFFFFu, cs[j], off);
                cq[j] += __shfl_xor_sync(0xFFFFFFFFu, cq[j], off);
            }
        if (lane < 4) {
#pragma unroll
            for (int j = 0; j < 8; ++j) {
                int cl = (j >> 1) * 8 + lane * 2 + (j & 1);
                scs[wid][cl] = cs[j];
                scq[wid][cl] = cq[j];
            }
        }
        __syncthreads();
        if (tid < 128) {
            int cl = tid & 31, w = tid >> 5;
            float s = scs[w][cl] + scs[w + 4][cl];
            float q = scq[w][cl] + scq[w + 4][cl];
            g_psum[(size_t)blockIdx.y * C3 + n0 + tid] = s;
            g_psq [(size_t)blockIdx.y * C3 + n0 + tid] = q;
        }
    }

    // ---- write C ----
    const int mrow = wm * 64 + (lane >> 2);
    const int ncol = wn * 32 + (lane & 3) * 2;
#pragma unroll
    for (int mi = 0; mi < 4; ++mi) {
#pragma unroll
        for (int ni = 0; ni < 4; ++ni) {
            int col = n0 + ncol + ni * 8;
            size_t r0 = (size_t)(m0 + mrow + mi * 16) * ldC + col;
            size_t r1 = r0 + 8 * (size_t)ldC;
            float2 v0, v1;
            v0.x = acc[mi][ni][0]; v0.y = acc[mi][ni][1];
            v1.x = acc[mi][ni][2]; v1.y = acc[mi][ni][3];
            if (BIAS) {
                float b0 = bias[col], b1 = bias[col + 1];
                v0.x += b0; v0.y += b1; v1.x += b0; v1.y += b1;
            }
            *(float2*)(C + r0) = v0;
            *(float2*)(C + r1) = v1;
        }
    }
#undef LOAD_STAGE
}

// ---------------- BN finalize: reduce 64 row-block partials ----------------
__global__ __launch_bounds__(256)
void bn_finalize(const float* __restrict__ gamma, const float* __restrict__ beta)
{
    int c = blockIdx.x * 256 + threadIdx.x;
    float s = 0.f, q = 0.f;
    for (int i = 0; i < 64; ++i) { s += g_psum[(size_t)i * C3 + c]; q += g_psq[(size_t)i * C3 + c]; }
    float mean = s * (1.f / M_);
    float var  = q * (1.f / M_) - mean * mean;
    float rs   = rsqrtf(var + 1e-5f);
    float sc   = gamma[c] * rs;
    g_scale[c] = sc;
    g_shift[c] = beta[c] - mean * sc;
}

// ---------------- fused BN-apply + multistep LIF + bit-pack ----------------
__global__ __launch_bounds__(256)
void bnlif(const float* __restrict__ qkv)
{
    int gid   = blockIdx.x * 256 + threadIdx.x;
    int n     = gid & 1023;
    int t     = gid >> 10;
    int h     = t % H_;
    int which = t / H_;
    int c0    = which * C_ + h * D_;

    u64 bits[B_];
#pragma unroll
    for (int b = 0; b < B_; ++b) bits[b] = 0ull;

#pragma unroll
    for (int dq = 0; dq < 4; ++dq) {
        int cb = c0 + dq * 16;
        float sc[16], sh[16];
#pragma unroll
        for (int q4 = 0; q4 < 4; ++q4) {
            *(float4*)(sc + q4 * 4) = *(const float4*)(g_scale + cb + q4 * 4);
            *(float4*)(sh + q4 * 4) = *(const float4*)(g_shift + cb + q4 * 4);
        }
        float v[16];
#pragma unroll
        for (int d = 0; d < 16; ++d) v[d] = 0.f;

#pragma unroll
        for (int b = 0; b < B_; ++b) {
            const float* row = qkv + (size_t)(b * N_ + n) * C3 + cb;
            float xv[16];
#pragma unroll
            for (int q4 = 0; q4 < 4; ++q4)
                *(float4*)(xv + q4 * 4) = *(const float4*)(row + q4 * 4);
#pragma unroll
            for (int d = 0; d < 16; ++d) {
                float y = fmaf(xv[d], sc[d], sh[d]);
                v[d] = 0.5f * (v[d] + y);
                if (v[d] >= 1.0f) {
                    bits[b] |= 1ull << (dq * 16 + d);
                    v[d] = 0.f;
                }
            }
        }
    }
#pragma unroll
    for (int b = 0; b < B_; ++b)
        g_sbits[((size_t)(which * B_ + b) * H_ + h) * N_ + n] = bits[b];
}

// ============== attention v2: full tensor-core (QK mma, exp, PV mma) ========
#define A2_Q    0                       // 128 x 72 halves
#define A2_K    18432                   // 128 x 72 halves
#define A2_VT   36864                   // 96 x 136 halves
#define A2_EH   62976                   // 128 x 136 halves
#define A2_EL   97792                   // 128 x 136 halves
#define A2_DEN  132608                  // 128 floats
#define ATTN2_SMEM 133120

__global__ __launch_bounds__(256)
void attn2(__half* __restrict__ ohi, __half* __restrict__ olo)
{
    extern __shared__ char sm[];
    const u32 base = smem_to_u32(sm);
    const int tid = threadIdx.x, lane = tid & 31, wid = tid >> 5;
    const int bh = blockIdx.x, rt = blockIdx.y;
    const int b = bh / H_, h = bh % H_;

    const u64* qb = g_sbits + ((size_t)(0 * B_ + b) * H_ + h) * N_ + rt * 128;
    const u64* kb = g_sbits + ((size_t)(1 * B_ + b) * H_ + h) * N_;
    const u64* vb = g_sbits + ((size_t)(2 * B_ + b) * H_ + h) * N_;

    __half* sQ  = (__half*)(sm + A2_Q);
    __half* sK  = (__half*)(sm + A2_K);
    __half* sVt = (__half*)(sm + A2_VT);
    __half* sEh = (__half*)(sm + A2_EH);
    __half* sEl = (__half*)(sm + A2_EL);
    float*  den = (float*)(sm + A2_DEN);

    const int iA = lane & 7, jA = lane >> 3;
    const int mA = iA + (jA & 1) * 8;
    const int kA = (jA >> 1) * 8;
    const int nB = iA + (lane >> 4) * 8;
    const int kB = (jA & 1) * 8;

    const int wmQ = wid >> 2, wnQ = wid & 3;   // QK: 2x4
    const int wmP = wid >> 1, wnP = wid & 1;   // PV: 4x2

    {
        int j = tid >> 1, hs = tid & 1;
        u64 qr = qb[j] >> (hs * 32);
        __half* dst = sQ + j * 72 + hs * 32;
#pragma unroll
        for (int d = 0; d < 32; ++d)
            dst[d] = __float2half_rn((float)((qr >> d) & 1ull));
    }

    float oacc[2][5][4];
#pragma unroll
    for (int mi = 0; mi < 2; ++mi)
#pragma unroll
        for (int ni = 0; ni < 5; ++ni)
#pragma unroll
            for (int k = 0; k < 4; ++k) oacc[mi][ni][k] = 0.f;

    for (int jt = 0; jt < 8; ++jt) {
        {
            int j = tid >> 1, hs = tid & 1;
            u64 kr = kb[jt * 128 + j] >> (hs * 32);
            __half* dst = sK + j * 72 + hs * 32;
#pragma unroll
            for (int d = 0; d < 32; ++d)
                dst[d] = __float2half_rn((float)((kr >> d) & 1ull));
        }
#pragma unroll 4
        for (int it = 0; it < 48; ++it) {
            int idx = it * 256 + tid;
            int d = idx >> 7, j = idx & 127;
            float v = 0.f;
            if (d < 64) v = (float)((vb[jt * 128 + j] >> d) & 1ull);
            else if (d == 64) v = 1.f;
            sVt[d * 136 + j] = __float2half_rn(v);
        }
        __syncthreads();

#pragma unroll
        for (int nh = 0; nh < 2; ++nh) {
            float sacc[4][2][4];
#pragma unroll
            for (int mi = 0; mi < 4; ++mi)
#pragma unroll
                for (int nj = 0; nj < 2; ++nj)
#pragma unroll
                    for (int k = 0; k < 4; ++k) sacc[mi][nj][k] = 0.f;
#pragma unroll
            for (int ks = 0; ks < 4; ++ks) {
                u32 aq[4][4], bk[4];
#pragma unroll
                for (int mi = 0; mi < 4; ++mi)
                    ldsm4(aq[mi], base + A2_Q +
                          (u32)(((wmQ * 64 + mi * 16 + mA) * 72 + ks * 16 + kA) * 2));
                ldsm4(bk, base + A2_K +
                      (u32)(((wnQ * 32 + nh * 16 + nB) * 72 + ks * 16 + kB) * 2));
#pragma unroll
                for (int mi = 0; mi < 4; ++mi)
#pragma unroll
                    for (int nj = 0; nj < 2; ++nj)
                        mma_f16(sacc[mi][nj], aq[mi], &bk[nj * 2]);
            }
            const float CEXP = 0.18033688011f;   // log2(e)/8
#pragma unroll
            for (int mi = 0; mi < 4; ++mi)
#pragma unroll
                for (int nj = 0; nj < 2; ++nj) {
                    int r0 = wmQ * 64 + mi * 16 + (lane >> 2);
                    int c0 = wnQ * 32 + nh * 16 + nj * 8 + (lane & 3) * 2;
                    float e0 = exp2f(sacc[mi][nj][0] * CEXP);
                    float e1 = exp2f(sacc[mi][nj][1] * CEXP);
                    float e2 = exp2f(sacc[mi][nj][2] * CEXP);
                    float e3 = exp2f(sacc[mi][nj][3] * CEXP);
                    __half h0 = __float2half_rn(e0), h1 = __float2half_rn(e1);
                    __half h2 = __float2half_rn(e2), h3 = __float2half_rn(e3);
                    __half2 p;
                    p.x = h0; p.y = h1; *(__half2*)(sEh + r0 * 136 + c0) = p;
                    p.x = h2; p.y = h3; *(__half2*)(sEh + (r0 + 8) * 136 + c0) = p;
                    p.x = __float2half_rn(e0 - __half2float(h0));
                    p.y = __float2half_rn(e1 - __half2float(h1));
                    *(__half2*)(sEl + r0 * 136 + c0) = p;
                    p.x = __float2half_rn(e2 - __half2float(h2));
                    p.y = __float2half_rn(e3 - __half2float(h3));
                    *(__half2*)(sEl + (r0 + 8) * 136 + c0) = p;
                }
        }
        __syncthreads();

#pragma unroll
        for (int ks = 0; ks < 8; ++ks) {
            u32 aeh[2][4], ael[2][4], bv[3][4];
#pragma unroll
            for (int mi = 0; mi < 2; ++mi) {
                u32 ro = (u32)(((wmP * 32 + mi * 16 + mA) * 136 + ks * 16 + kA) * 2);
                ldsm4(aeh[mi], base + A2_EH + ro);
                ldsm4(ael[mi], base + A2_EL + ro);
            }
#pragma unroll
            for (int p = 0; p < 3; ++p)
                ldsm4(bv[p], base + A2_VT +
                      (u32)(((wnP * 40 + p * 16 + nB) * 136 + ks * 16 + kB) * 2));
#pragma unroll
            for (int mi = 0; mi < 2; ++mi)
#pragma unroll
                for (int ni = 0; ni < 5; ++ni) {
                    const u32* bb = (ni < 4) ? &bv[ni >> 1][(ni & 1) * 2] : &bv[2][0];
                    mma_f16(oacc[mi][ni], aeh[mi], bb);
                    mma_f16(oacc[mi][ni], ael[mi], bb);
                }
        }
        __syncthreads();
    }

    if (wnP == 1 && (lane & 3) == 0) {
#pragma unroll
        for (int mi = 0; mi < 2; ++mi) {
            int r0 = wmP * 32 + mi * 16 + (lane >> 2);
            den[r0]     = oacc[mi][3][0];
            den[r0 + 8] = oacc[mi][3][2];
        }
    }
    __syncthreads();

    const int nlim = (wnP == 0) ? 5 : 3;
#pragma unroll
    for (int mi = 0; mi < 2; ++mi) {
        int r0 = wmP * 32 + mi * 16 + (lane >> 2);
        float i0 = 1.f / den[r0], i1 = 1.f / den[r0 + 8];
        size_t gr0 = ((size_t)(b * N_ + rt * 128 + r0)) * C_ + h * 64;
        size_t gr1 = gr0 + 8 * (size_t)C_;
#pragma unroll
        for (int ni = 0; ni < 5; ++ni) {
            if (ni >= nlim) break;
            int c0 = wnP * 40 + ni * 8 + (lane & 3) * 2;
            float v0 = oacc[mi][ni][0] * i0, v1 = oacc[mi][ni][1] * i0;
            float v2 = oacc[mi][ni][2] * i1, v3 = oacc[mi][ni][3] * i1;
            __half h0 = __float2half_rn(v0), h1 = __float2half_rn(v1);
            __half h2 = __float2half_rn(v2), h3 = __float2half_rn(v3);
            __half2 p;
            p.x = h0; p.y = h1; *(__half2*)(ohi + gr0 + c0) = p;
            p.x = h2; p.y = h3; *(__half2*)(ohi + gr1 + c0) = p;
            p.x = __float2half_rn(v0 - __half2float(h0));
            p.y = __float2half_rn(v1 - __half2float(h1));
            *(__half2*)(olo + gr0 + c0) = p;
            p.x = __float2half_rn(v2 - __half2float(h2));
            p.y = __float2half_rn(v3 - __half2float(h3));
            *(__half2*)(olo + gr1 + c0) = p;
        }
    }
}

// ---------------- launch ----------------------------------------------------
extern "C" void kernel_launch(void* const* d_in, const int* in_sizes, int n_in,
                              void* d_out, int out_size)
{
    const float* x      = (const float*)d_in[0];
    const float* w_qkv  = (const float*)d_in[1];
    const float* gamma  = (const float*)d_in[2];
    const float* beta   = (const float*)d_in[3];
    const float* w_proj = (const float*)d_in[4];
    const float* b_proj = (const float*)d_in[5];
    float* out = (float*)d_out;

    float *qkv = nullptr;
    __half *xhi, *xlo, *w1hi, *w1lo, *ahi, *alo, *w2hi, *w2lo;
    cudaGetSymbolAddress((void**)&qkv,  g_qkv);
    cudaGetSymbolAddress((void**)&xhi,  g_xhi);
    cudaGetSymbolAddress((void**)&xlo,  g_xlo);
    cudaGetSymbolAddress((void**)&w1hi, g_w1hi);
    cudaGetSymbolAddress((void**)&w1lo, g_w1lo);
    cudaGetSymbolAddress((void**)&ahi,  g_ahi);
    cudaGetSymbolAddress((void**)&alo,  g_alo);
    cudaGetSymbolAddress((void**)&w2hi, g_w2hi);
    cudaGetSymbolAddress((void**)&w2lo, g_w2lo);

    cudaFuncSetAttribute(attn2,
                         cudaFuncAttributeMaxDynamicSharedMemorySize, ATTN2_SMEM);
    cudaFuncSetAttribute(gemm_mma<false, true>,
                         cudaFuncAttributeMaxDynamicSharedMemorySize, GEMM_SMEM);
    cudaFuncSetAttribute(gemm_mma<true, false>,
                         cudaFuncAttributeMaxDynamicSharedMemorySize, GEMM_SMEM);

    // 0) fp16 splits of x, w_qkv, w_proj
    split_f16<<<(M_ * C_ / 4 + 255) / 256, 256>>>(x, xhi, xlo, M_ * C_ / 4);
    split_f16<<<(C3 * C_ / 4 + 255) / 256, 256>>>(w_qkv, w1hi, w1lo, C3 * C_ / 4);
    split_f16<<<(C_ * C_ / 4 + 255) / 256, 256>>>(w_proj, w2hi, w2lo, C_ * C_ / 4);
    // 1) qkv = x @ w_qkv^T (mma.sync split-fp16) + fused BN stage-1 partials
    gemm_mma<false, true><<<dim3(C3 / 128, M_ / 128), 256, GEMM_SMEM>>>(
        xhi, xlo, w1hi, w1lo, nullptr, qkv, C3);
    // 2) BN finalize (reduce 64 row-block partials)
    bn_finalize<<<9, 256>>>(gamma, beta);
    // 3) BN apply + LIF + bit-pack
    bnlif<<<144, 256>>>(qkv);
    // 4) tensor-core spiking attention -> fp16 split output
    attn2<<<dim3(B_ * H_, 8), 256, ATTN2_SMEM>>>(ahi, alo);
    // 5) out = attn @ w_proj^T + b_proj (mma.sync split-fp16)
    gemm_mma<true, false><<<dim3(C_ / 128, M_ / 128), 256, GEMM_SMEM>>>(
        ahi, alo, w2hi, w2lo, b_proj, out, C_);
}